// round 9
// baseline (speedup 1.0000x reference)
#include <cuda_runtime.h>
#include <cuda_bf16.h>
#include <stdint.h>

// ContextAwareTracker: LSTM enc(50)+dec(12), B=16384, H=128, I=5.
// Round 9: R8 math/layout unchanged. Fix register starvation: the iter loop
// was fully unrolled by ptxas -> c_loc promoted to 64 regs + 8 iters of frags
// hoisted -> 255-reg cap, spills, no LDSM/MMA pipelining (issue 21%).
// "#pragma unroll 1" on iter (and t) demotes c_loc to local (cheap, off the
// critical path) and frees regs so ptxas can pipeline kt stages.
// NOTE: tcgen05 unavailable (harness PTX target sm_103 base) - mma.sync only.

#define BDIM 256
#define KP   152          // A k-pad: 304B row stride (19x16B, odd -> conflict-free LDSM)
#define ROWB 304
#define KW   144          // W k-pad: 288B row stride
#define WROWB 288
#define ABUF 38912        // 128 * 304 (one split, one buffer)
#define SM_W (4 * ABUF)   // 155648; A: [buf 2][split 2][128][KP]
#define WBLK 36864        // 64 cols x 2 splits x 288B
#define SMEM_TOTAL (SM_W + 2 * WBLK)   // 229376 <= 232448
#define NBLOCKS 496       // 62 steps * 8 chunk-iters

__device__ __nv_bfloat16 g_wpack[16 * 18432];  // [net 2][chunk64 8][split 2][n 64][k 144]

// gate col interleave: C = 4*unit + gate (0=i,1=f,2=g,3=o)
__global__ void prep_kernel(const float* __restrict__ eWih, const float* __restrict__ eWhh,
                            const float* __restrict__ ebih, const float* __restrict__ ebhh,
                            const float* __restrict__ dWih, const float* __restrict__ dWhh,
                            const float* __restrict__ dbih, const float* __restrict__ dbhh)
{
    int idx = blockIdx.x * blockDim.x + threadIdx.x;
    if (idx >= 16 * 18432) return;
    int block = idx / 18432;
    int e     = idx % 18432;
    int split = e / 9216;
    int r     = (e % 9216) / 144;
    int k     = e % 144;
    int net = block >> 3, chunk = block & 7;
    int C = chunk * 64 + r;
    int u = C >> 2, g = C & 3;
    int j = g * 128 + u;
    const float* Wih = net ? dWih : eWih;
    const float* Whh = net ? dWhh : eWhh;
    const float* bih = net ? dbih : ebih;
    const float* bhh = net ? dbhh : ebhh;
    float w = 0.f;
    if (k < 128)       w = Whh[j * 128 + k];
    else if (k < 133)  w = Wih[j * 5 + (k - 128)];
    else if (k == 133) w = bih[j] + bhh[j];      // bias lane (A has 1.0 at k=133)
    __nv_bfloat16 hi = __float2bfloat16_rn(w);
    __nv_bfloat16 v  = split ? __float2bfloat16_rn(w - __bfloat162float(hi)) : hi;
    g_wpack[(size_t)block * 18432 + e] = v;
}

__device__ __forceinline__ uint32_t smem_u32(const void* p) {
    uint32_t a;
    asm("{ .reg .u64 t; cvta.to.shared.u64 t, %1; cvt.u32.u64 %0, t; }" : "=r"(a) : "l"(p));
    return a;
}
__device__ __forceinline__ float sigf(float v)   { return __fdividef(1.f, 1.f + __expf(-v)); }
__device__ __forceinline__ float tanhf_(float v) { return fmaf(2.f, sigf(2.f * v), -1.f); }
__device__ __forceinline__ unsigned short bfu(float v) {
    return __bfloat16_as_ushort(__float2bfloat16_rn(v));
}
__device__ __forceinline__ float ubf(unsigned short u) {
    return __bfloat162float(__ushort_as_bfloat16(u));
}

#define LDSX4(r, addr) \
    asm volatile("ldmatrix.sync.aligned.m8n8.x4.shared.b16 {%0,%1,%2,%3}, [%4];" \
        : "=r"((r)[0]), "=r"((r)[1]), "=r"((r)[2]), "=r"((r)[3]) : "r"(addr) : "memory")

#define MMA16816(d, a, b0, b1) \
    asm volatile("mma.sync.aligned.m16n8k16.row.col.f32.bf16.bf16.f32 " \
        "{%0,%1,%2,%3},{%4,%5,%6,%7},{%8,%9},{%0,%1,%2,%3};" \
        : "+f"((d)[0]), "+f"((d)[1]), "+f"((d)[2]), "+f"((d)[3]) \
        : "r"((a)[0]), "r"((a)[1]), "r"((a)[2]), "r"((a)[3]), "r"(b0), "r"(b1))

__device__ __forceinline__ void cp_block(int lin, uint32_t dst, int tid) {
    int gblock = ((lin >= 400) ? 8 : 0) + (lin & 7);
    const char* src = (const char*)g_wpack + (size_t)gblock * WBLK + tid * 16;
    uint32_t d = dst + tid * 16;
    #pragma unroll
    for (int i = 0; i < 9; i++) {   // 2304 x 16B = 9 * 256 threads
        asm volatile("cp.async.ca.shared.global [%0], [%1], 16;"
                     :: "r"(d + i * 4096), "l"(src + i * 4096) : "memory");
    }
    asm volatile("cp.async.commit_group;" ::: "memory");
}

__global__ void __launch_bounds__(BDIM, 1)
lstm_mma(const float* __restrict__ x,
         const float* __restrict__ linW,
         const float* __restrict__ linb,
         float* __restrict__ out)
{
    extern __shared__ char smem[];
    const uint32_t sb = smem_u32(smem);
    const int tid  = threadIdx.x;
    const int lane = tid & 31;
    const int w    = tid >> 5;
    const int mq   = w & 3;          // M quarter: rows mq*32..+31
    const int nh   = w >> 2;         // N half within 64-col chunk: cols nh*32..+31
    const int base_row = blockIdx.x * 128;

    // zero all smem (h=0, x pad lanes=0)
    {
        uint4 z = make_uint4(0, 0, 0, 0);
        uint4* p = (uint4*)smem;
        for (int i = tid; i < SMEM_TOTAL / 16; i += BDIM) p[i] = z;
    }
    __syncthreads();
    if (tid < 128) {    // bias lane k=133 = 1.0 (hi) in both buffers
        *(unsigned short*)(smem + 0 * ABUF + tid * ROWB + 266) = 0x3F80;
        *(unsigned short*)(smem + 2 * ABUF + tid * ROWB + 266) = 0x3F80;
    }

    // cell state: dynamic indexing (iter not unrolled) -> local memory by
    // design; 16 LDL + 8 STL per thread per step, off the critical path.
    float c_loc[64];
    #pragma unroll
    for (int i = 0; i < 64; i++) c_loc[i] = 0.f;

    cp_block(0, sb + SM_W, tid);
    __syncthreads();

    int cur = 0;
    #pragma unroll 1
    for (int t = 0; t < 62; t++) {
        const int nb = cur ^ 1;

        // stage x(t) into k=128..132 of current buffer (t==49: both buffers,
        // providing ctx + last_velocity for the decoder's dec_in0)
        if (t < 50 && tid < 128) {
            const float* xp = x + (size_t)(base_row + tid) * 250 + (size_t)t * 5;
            float v[5] = { xp[0], xp[1], xp[2], xp[3], xp[4] };
            #pragma unroll
            for (int b = 0; b < 2; b++) {
                if (b == 1 && t != 49) break;
                int bsel = b == 0 ? cur : nb;
                char* bh = smem + bsel * 2 * ABUF + tid * ROWB + 256;  // k=128
                #pragma unroll
                for (int i = 0; i < 5; i++) {
                    unsigned short hu = bfu(v[i]);
                    *(unsigned short*)(bh + i * 2) = hu;
                    *(unsigned short*)(bh + ABUF + i * 2) = bfu(v[i] - ubf(hu));
                }
            }
        }

        #pragma unroll 1
        for (int iter = 0; iter < 8; iter++) {
            const int lin = t * 8 + iter;
            // block lin was prefetched in the previous iter; ensure landed.
            asm volatile("cp.async.wait_group 0;" ::: "memory");
            __syncthreads();
            // prefetch next block; safe: barrier above separates all reads of
            // slot (lin+1)&1 for block lin-1 from these writes.
            {
                int nl = lin + 1; if (nl > NBLOCKS - 1) nl = NBLOCKS - 1;
                cp_block(nl, sb + SM_W + (uint32_t)(nl & 1) * WBLK, tid);
            }

            const uint32_t wb = sb + SM_W + (uint32_t)(lin & 1) * WBLK;
            const uint32_t ab = sb + (uint32_t)cur * 2 * ABUF;

            float acc[2][4][4];
            #pragma unroll
            for (int mt = 0; mt < 2; mt++)
                #pragma unroll
                for (int nt = 0; nt < 4; nt++)
                    #pragma unroll
                    for (int q = 0; q < 4; q++) acc[mt][nt][q] = 0.f;

            #pragma unroll
            for (int kt = 0; kt < 9; kt++) {
                uint32_t ah[2][4], al[2][4], bh_[2][4], bl_[2][4];
                const uint32_t kofA = (uint32_t)((kt * 16 + ((lane >> 4) << 3)) << 1);
                const uint32_t kofB = (uint32_t)((kt * 16 + (lane & 8)) << 1);
                #pragma unroll
                for (int p = 0; p < 2; p++) {
                    uint32_t rn = (uint32_t)(nh * 32 + p * 16 + ((lane >> 4) << 3)
                                  + (lane & 7)) * WROWB + kofB;
                    LDSX4(bh_[p], wb + rn);
                    LDSX4(bl_[p], wb + 18432 + rn);
                }
                #pragma unroll
                for (int mt = 0; mt < 2; mt++) {
                    uint32_t ra = ab + (uint32_t)(mq * 32 + mt * 16 + (lane & 15)) * ROWB + kofA;
                    LDSX4(ah[mt], ra);
                    LDSX4(al[mt], ra + ABUF);
                }
                // 3 sweeps over 8 independent tiles: dep distance 8
                #pragma unroll
                for (int mt = 0; mt < 2; mt++)
                    #pragma unroll
                    for (int nt = 0; nt < 4; nt++)
                        MMA16816(acc[mt][nt], ah[mt],
                                 bh_[nt >> 1][(nt & 1) * 2], bh_[nt >> 1][(nt & 1) * 2 + 1]);
                #pragma unroll
                for (int mt = 0; mt < 2; mt++)
                    #pragma unroll
                    for (int nt = 0; nt < 4; nt++)
                        MMA16816(acc[mt][nt], al[mt],
                                 bh_[nt >> 1][(nt & 1) * 2], bh_[nt >> 1][(nt & 1) * 2 + 1]);
                #pragma unroll
                for (int mt = 0; mt < 2; mt++)
                    #pragma unroll
                    for (int nt = 0; nt < 4; nt++)
                        MMA16816(acc[mt][nt], ah[mt],
                                 bl_[nt >> 1][(nt & 1) * 2], bl_[nt >> 1][(nt & 1) * 2 + 1]);
            }

            // epilogue: warp owns rows [mq*32..+31], units [iter*16+nh*8..+7]
            const int cb_u = iter * 16 + nh * 8;
            const bool even = !(lane & 1);
            #pragma unroll
            for (int mt = 0; mt < 2; mt++) {
                #pragma unroll
                for (int nt = 0; nt < 4; nt++) {
                    float c0 = acc[mt][nt][0], c1 = acc[mt][nt][1];
                    float c2 = acc[mt][nt][2], c3 = acc[mt][nt][3];
                    float x0 = __shfl_xor_sync(0xffffffffu, c0, 1);
                    float x1 = __shfl_xor_sync(0xffffffffu, c1, 1);
                    float x2 = __shfl_xor_sync(0xffffffffu, c2, 1);
                    float x3 = __shfl_xor_sync(0xffffffffu, c3, 1);
                    float iv = even ? c0 : x2;
                    float fv = even ? c1 : x3;
                    float gv = even ? x0 : c2;
                    float ov = even ? x1 : c3;
                    int row = mq * 32 + mt * 16 + (lane >> 2) + (even ? 0 : 8);
                    int ug  = cb_u + nt * 2 + ((lane & 3) >> 1);
                    int ci  = iter * 8 + mt * 4 + nt;
                    float ivs = sigf(iv), fvs = sigf(fv);
                    float gvt = tanhf_(gv), ovs = sigf(ov);
                    float cn = fmaf(fvs, c_loc[ci], ivs * gvt);
                    c_loc[ci] = cn;
                    float hv = ovs * tanhf_(cn);
                    unsigned short hu = bfu(hv);
                    char* bh = smem + nb * 2 * ABUF + row * ROWB + ug * 2;
                    *(unsigned short*)bh = hu;
                    *(unsigned short*)(bh + ABUF) = bfu(hv - ubf(hu));
                }
            }
        }

        if (t >= 50) {   // pred = h_new @ linW^T + linb; feed back velocity
            __syncthreads();   // all epilogue writes of this step visible
            int r = tid & 127, jj = tid >> 7;
            const char* bh = smem + nb * 2 * ABUF + r * ROWB;
            float accp = __ldg(linb + jj);
            const float* lw = linW + jj * 128;
            #pragma unroll 16
            for (int u = 0; u < 128; u++) {
                float hv = ubf(*(const unsigned short*)(bh + u * 2))
                         + ubf(*(const unsigned short*)(bh + ABUF + u * 2));
                accp = fmaf(hv, __ldg(lw + u), accp);
            }
            out[((size_t)(base_row + r) * 12 + (t - 50)) * 2 + jj] = accp;
            unsigned short hu = bfu(accp);
            char* bx = smem + nb * 2 * ABUF + r * ROWB + (128 + jj) * 2;
            *(unsigned short*)bx = hu;
            *(unsigned short*)(bx + ABUF) = bfu(accp - ubf(hu));
        }

        cur = nb;
    }
}

extern "C" void kernel_launch(void* const* d_in, const int* in_sizes, int n_in,
                              void* d_out, int out_size)
{
    const float* x    = (const float*)d_in[0];
    const float* eWih = (const float*)d_in[1];
    const float* eWhh = (const float*)d_in[2];
    const float* ebih = (const float*)d_in[3];
    const float* ebhh = (const float*)d_in[4];
    const float* dWih = (const float*)d_in[5];
    const float* dWhh = (const float*)d_in[6];
    const float* dbih = (const float*)d_in[7];
    const float* dbhh = (const float*)d_in[8];
    const float* lW   = (const float*)d_in[9];
    const float* lb   = (const float*)d_in[10];
    float* out = (float*)d_out;

    cudaFuncSetAttribute(lstm_mma, cudaFuncAttributeMaxDynamicSharedMemorySize, SMEM_TOTAL);

    prep_kernel<<<(16 * 18432 + 255) / 256, 256>>>(eWih, eWhh, ebih, ebhh,
                                                   dWih, dWhh, dbih, dbhh);
    lstm_mma<<<128, BDIM, SMEM_TOTAL>>>(x, lW, lb, out);
}

// round 10
// speedup vs baseline: 1.0805x; 1.0805x over previous
#include <cuda_runtime.h>
#include <cuda_bf16.h>
#include <stdint.h>

// ContextAwareTracker: LSTM enc(50)+dec(12), B=16384, H=128, I=5.
// Round 10: R9 math/layout unchanged; occupancy fix. R7-R9 were latency-bound
// (occ 12.5%, 2 warps/SMSP; tensor 35%, issue 21%, nothing saturated).
// 512 threads/CTA -> 16 warps (4/SMSP); warp tile 32x32 -> 32x16 so per-warp
// regs fit the 128-reg budget (64K/512). Same smem, same 3-term hi/lo bf16
// mma.sync, same per-iter cp.async W double-buffer.
// NOTE: tcgen05 unavailable (harness PTX target sm_103 base) - mma.sync only.

#define BDIM 512
#define KP   152          // A k-pad: 304B row stride (conflict-free LDSM)
#define ROWB 304
#define KW   144          // W k-pad: 288B row stride
#define WROWB 288
#define ABUF 38912        // 128 * 304 (one split, one buffer)
#define SM_W (4 * ABUF)   // 155648; A: [buf 2][split 2][128][KP]
#define WBLK 36864        // 64 cols x 2 splits x 288B
#define SMEM_TOTAL (SM_W + 2 * WBLK)   // 229376 <= 232448
#define NBLOCKS 496       // 62 steps * 8 chunk-iters

__device__ __nv_bfloat16 g_wpack[16 * 18432];  // [net 2][chunk64 8][split 2][n 64][k 144]

// gate col interleave: C = 4*unit + gate (0=i,1=f,2=g,3=o)
__global__ void prep_kernel(const float* __restrict__ eWih, const float* __restrict__ eWhh,
                            const float* __restrict__ ebih, const float* __restrict__ ebhh,
                            const float* __restrict__ dWih, const float* __restrict__ dWhh,
                            const float* __restrict__ dbih, const float* __restrict__ dbhh)
{
    int idx = blockIdx.x * blockDim.x + threadIdx.x;
    if (idx >= 16 * 18432) return;
    int block = idx / 18432;
    int e     = idx % 18432;
    int split = e / 9216;
    int r     = (e % 9216) / 144;
    int k     = e % 144;
    int net = block >> 3, chunk = block & 7;
    int C = chunk * 64 + r;
    int u = C >> 2, g = C & 3;
    int j = g * 128 + u;
    const float* Wih = net ? dWih : eWih;
    const float* Whh = net ? dWhh : eWhh;
    const float* bih = net ? dbih : ebih;
    const float* bhh = net ? dbhh : ebhh;
    float w = 0.f;
    if (k < 128)       w = Whh[j * 128 + k];
    else if (k < 133)  w = Wih[j * 5 + (k - 128)];
    else if (k == 133) w = bih[j] + bhh[j];      // bias lane (A has 1.0 at k=133)
    __nv_bfloat16 hi = __float2bfloat16_rn(w);
    __nv_bfloat16 v  = split ? __float2bfloat16_rn(w - __bfloat162float(hi)) : hi;
    g_wpack[(size_t)block * 18432 + e] = v;
}

__device__ __forceinline__ uint32_t smem_u32(const void* p) {
    uint32_t a;
    asm("{ .reg .u64 t; cvta.to.shared.u64 t, %1; cvt.u32.u64 %0, t; }" : "=r"(a) : "l"(p));
    return a;
}
__device__ __forceinline__ float sigf(float v)   { return __fdividef(1.f, 1.f + __expf(-v)); }
__device__ __forceinline__ float tanhf_(float v) { return fmaf(2.f, sigf(2.f * v), -1.f); }
__device__ __forceinline__ unsigned short bfu(float v) {
    return __bfloat16_as_ushort(__float2bfloat16_rn(v));
}
__device__ __forceinline__ float ubf(unsigned short u) {
    return __bfloat162float(__ushort_as_bfloat16(u));
}

#define LDSX4(r, addr) \
    asm volatile("ldmatrix.sync.aligned.m8n8.x4.shared.b16 {%0,%1,%2,%3}, [%4];" \
        : "=r"((r)[0]), "=r"((r)[1]), "=r"((r)[2]), "=r"((r)[3]) : "r"(addr) : "memory")

#define MMA16816(d, a, b0, b1) \
    asm volatile("mma.sync.aligned.m16n8k16.row.col.f32.bf16.bf16.f32 " \
        "{%0,%1,%2,%3},{%4,%5,%6,%7},{%8,%9},{%0,%1,%2,%3};" \
        : "+f"((d)[0]), "+f"((d)[1]), "+f"((d)[2]), "+f"((d)[3]) \
        : "r"((a)[0]), "r"((a)[1]), "r"((a)[2]), "r"((a)[3]), "r"(b0), "r"(b1))

__device__ __forceinline__ void cp_block(int lin, uint32_t dst, int tid) {
    int gblock = ((lin >= 400) ? 8 : 0) + (lin & 7);
    const char* src = (const char*)g_wpack + (size_t)gblock * WBLK;
    #pragma unroll
    for (int i = 0; i < 5; i++) {   // 2304 x 16B over 512 threads
        int idx = tid + i * BDIM;
        if (idx < 2304) {
            asm volatile("cp.async.ca.shared.global [%0], [%1], 16;"
                         :: "r"(dst + idx * 16), "l"(src + idx * 16) : "memory");
        }
    }
    asm volatile("cp.async.commit_group;" ::: "memory");
}

__global__ void __launch_bounds__(BDIM, 1)
lstm_mma(const float* __restrict__ x,
         const float* __restrict__ linW,
         const float* __restrict__ linb,
         float* __restrict__ out)
{
    extern __shared__ char smem[];
    const uint32_t sb = smem_u32(smem);
    const int tid  = threadIdx.x;
    const int lane = tid & 31;
    const int w    = tid >> 5;       // 0..15
    const int mq   = w & 3;          // M quarter: rows mq*32..+31
    const int nh   = w >> 2;         // N sixteenth-block: cols nh*16..+15 of 64-col chunk
    const int base_row = blockIdx.x * 128;

    // zero all smem (h=0, x pad lanes=0)
    {
        uint4 z = make_uint4(0, 0, 0, 0);
        uint4* p = (uint4*)smem;
        for (int i = tid; i < SMEM_TOTAL / 16; i += BDIM) p[i] = z;
    }
    __syncthreads();
    if (tid < 128) {    // bias lane k=133 = 1.0 (hi) in both buffers
        *(unsigned short*)(smem + 0 * ABUF + tid * ROWB + 266) = 0x3F80;
        *(unsigned short*)(smem + 2 * ABUF + tid * ROWB + 266) = 0x3F80;
    }

    // cell state: 4 cells per iter x 8 iters (dynamic iter -> local memory)
    float c_loc[32];
    #pragma unroll
    for (int i = 0; i < 32; i++) c_loc[i] = 0.f;

    cp_block(0, sb + SM_W, tid);
    __syncthreads();

    int cur = 0;
    #pragma unroll 1
    for (int t = 0; t < 62; t++) {
        const int nb = cur ^ 1;

        // stage x(t) into k=128..132 of current buffer (t==49: both buffers,
        // providing ctx + last_velocity for the decoder's dec_in0)
        if (t < 50 && tid < 128) {
            const float* xp = x + (size_t)(base_row + tid) * 250 + (size_t)t * 5;
            float v[5] = { xp[0], xp[1], xp[2], xp[3], xp[4] };
            #pragma unroll
            for (int b = 0; b < 2; b++) {
                if (b == 1 && t != 49) break;
                int bsel = b == 0 ? cur : nb;
                char* bh = smem + bsel * 2 * ABUF + tid * ROWB + 256;  // k=128
                #pragma unroll
                for (int i = 0; i < 5; i++) {
                    unsigned short hu = bfu(v[i]);
                    *(unsigned short*)(bh + i * 2) = hu;
                    *(unsigned short*)(bh + ABUF + i * 2) = bfu(v[i] - ubf(hu));
                }
            }
        }

        #pragma unroll 1
        for (int iter = 0; iter < 8; iter++) {
            const int lin = t * 8 + iter;
            // block lin was prefetched in the previous iter; ensure landed.
            asm volatile("cp.async.wait_group 0;" ::: "memory");
            __syncthreads();
            // prefetch next block; safe: barrier above separates all reads of
            // slot (lin+1)&1 for block lin-1 from these writes.
            {
                int nl = lin + 1; if (nl > NBLOCKS - 1) nl = NBLOCKS - 1;
                cp_block(nl, sb + SM_W + (uint32_t)(nl & 1) * WBLK, tid);
            }

            const uint32_t wb = sb + SM_W + (uint32_t)(lin & 1) * WBLK;
            const uint32_t ab = sb + (uint32_t)cur * 2 * ABUF;

            float acc[2][2][4];
            #pragma unroll
            for (int mt = 0; mt < 2; mt++)
                #pragma unroll
                for (int nt = 0; nt < 2; nt++)
                    #pragma unroll
                    for (int q = 0; q < 4; q++) acc[mt][nt][q] = 0.f;

            #pragma unroll
            for (int kt = 0; kt < 9; kt++) {
                uint32_t ah[2][4], al[2][4], bh_[4], bl_[4];
                const uint32_t kofA = (uint32_t)((kt * 16 + ((lane >> 4) << 3)) << 1);
                const uint32_t kofB = (uint32_t)((kt * 16 + (lane & 8)) << 1);
                {
                    uint32_t rn = (uint32_t)(nh * 16 + ((lane >> 4) << 3)
                                  + (lane & 7)) * WROWB + kofB;
                    LDSX4(bh_, wb + rn);
                    LDSX4(bl_, wb + 18432 + rn);
                }
                #pragma unroll
                for (int mt = 0; mt < 2; mt++) {
                    uint32_t ra = ab + (uint32_t)(mq * 32 + mt * 16 + (lane & 15)) * ROWB + kofA;
                    LDSX4(ah[mt], ra);
                    LDSX4(al[mt], ra + ABUF);
                }
                // 3 sweeps over 4 independent tiles
                #pragma unroll
                for (int mt = 0; mt < 2; mt++)
                    #pragma unroll
                    for (int nt = 0; nt < 2; nt++)
                        MMA16816(acc[mt][nt], ah[mt], bh_[nt * 2], bh_[nt * 2 + 1]);
                #pragma unroll
                for (int mt = 0; mt < 2; mt++)
                    #pragma unroll
                    for (int nt = 0; nt < 2; nt++)
                        MMA16816(acc[mt][nt], al[mt], bh_[nt * 2], bh_[nt * 2 + 1]);
                #pragma unroll
                for (int mt = 0; mt < 2; mt++)
                    #pragma unroll
                    for (int nt = 0; nt < 2; nt++)
                        MMA16816(acc[mt][nt], ah[mt], bl_[nt * 2], bl_[nt * 2 + 1]);
            }

            // epilogue: warp owns rows [mq*32..+31], units [iter*16+nh*4..+3]
            const int cb_u = iter * 16 + nh * 4;
            const bool even = !(lane & 1);
            #pragma unroll
            for (int mt = 0; mt < 2; mt++) {
                #pragma unroll
                for (int nt = 0; nt < 2; nt++) {
                    float c0 = acc[mt][nt][0], c1 = acc[mt][nt][1];
                    float c2 = acc[mt][nt][2], c3 = acc[mt][nt][3];
                    float x0 = __shfl_xor_sync(0xffffffffu, c0, 1);
                    float x1 = __shfl_xor_sync(0xffffffffu, c1, 1);
                    float x2 = __shfl_xor_sync(0xffffffffu, c2, 1);
                    float x3 = __shfl_xor_sync(0xffffffffu, c3, 1);
                    float iv = even ? c0 : x2;
                    float fv = even ? c1 : x3;
                    float gv = even ? x0 : c2;
                    float ov = even ? x1 : c3;
                    int row = mq * 32 + mt * 16 + (lane >> 2) + (even ? 0 : 8);
                    int ug  = cb_u + nt * 2 + ((lane & 3) >> 1);
                    int ci  = iter * 4 + mt * 2 + nt;
                    float ivs = sigf(iv), fvs = sigf(fv);
                    float gvt = tanhf_(gv), ovs = sigf(ov);
                    float cn = fmaf(fvs, c_loc[ci], ivs * gvt);
                    c_loc[ci] = cn;
                    float hv = ovs * tanhf_(cn);
                    unsigned short hu = bfu(hv);
                    char* bh = smem + nb * 2 * ABUF + row * ROWB + ug * 2;
                    *(unsigned short*)bh = hu;
                    *(unsigned short*)(bh + ABUF) = bfu(hv - ubf(hu));
                }
            }
        }

        if (t >= 50) {   // pred = h_new @ linW^T + linb; feed back velocity
            __syncthreads();   // all epilogue writes of this step visible
            if (tid < 256) {
                int r = tid & 127, jj = tid >> 7;
                const char* bh = smem + nb * 2 * ABUF + r * ROWB;
                float accp = __ldg(linb + jj);
                const float* lw = linW + jj * 128;
                #pragma unroll 16
                for (int u = 0; u < 128; u++) {
                    float hv = ubf(*(const unsigned short*)(bh + u * 2))
                             + ubf(*(const unsigned short*)(bh + ABUF + u * 2));
                    accp = fmaf(hv, __ldg(lw + u), accp);
                }
                out[((size_t)(base_row + r) * 12 + (t - 50)) * 2 + jj] = accp;
                unsigned short hu = bfu(accp);
                char* bx = smem + nb * 2 * ABUF + r * ROWB + (128 + jj) * 2;
                *(unsigned short*)bx = hu;
                *(unsigned short*)(bx + ABUF) = bfu(accp - ubf(hu));
            }
        }

        cur = nb;
    }
}

extern "C" void kernel_launch(void* const* d_in, const int* in_sizes, int n_in,
                              void* d_out, int out_size)
{
    const float* x    = (const float*)d_in[0];
    const float* eWih = (const float*)d_in[1];
    const float* eWhh = (const float*)d_in[2];
    const float* ebih = (const float*)d_in[3];
    const float* ebhh = (const float*)d_in[4];
    const float* dWih = (const float*)d_in[5];
    const float* dWhh = (const float*)d_in[6];
    const float* dbih = (const float*)d_in[7];
    const float* dbhh = (const float*)d_in[8];
    const float* lW   = (const float*)d_in[9];
    const float* lb   = (const float*)d_in[10];
    float* out = (float*)d_out;

    cudaFuncSetAttribute(lstm_mma, cudaFuncAttributeMaxDynamicSharedMemorySize, SMEM_TOTAL);

    prep_kernel<<<(16 * 18432 + 255) / 256, 256>>>(eWih, eWhh, ebih, ebhh,
                                                   dWih, dWhh, dbih, dbhh);
    lstm_mma<<<128, BDIM, SMEM_TOTAL>>>(x, lW, lb, out);
}

// round 11
// speedup vs baseline: 1.4172x; 1.3115x over previous
#include <cuda_runtime.h>
#include <cuda_bf16.h>
#include <stdint.h>

// ContextAwareTracker: LSTM enc(50)+dec(12), B=16384, H=128, I=5.
// Round 11: cut LDSM traffic (L1 was 68%, co-binder with tensor 38%).
//  - warp tile 16 rows x 32 cols (8 M-groups x 2 N-groups): each warp keeps
//    its full-K A fragments (hi+lo, 9kt x 8 regs = 72) in registers across
//    all 8 W-blocks -> A read from smem ONCE per step (was 8x, x4 dup).
//  - A single-buffered (frags in regs make it safe) -> smem 152KB, so B pads
//    to 304B row stride = conflict-free ldmatrix (288B was 2-way conflicted).
// Math identical to R7-R10: 3-term hi/lo bf16 mma.sync, fp32 accum.
// NOTE: tcgen05 unavailable (harness PTX target sm_103 base) - mma.sync only.

#define BDIM 512
#define ROWB 304          // 304%128=48 -> ldmatrix conflict-free; K pad 152
#define ABUF 38912        // 128 * 304 (one split)
#define SM_B (2 * ABUF)   // 77824: B double buffer
#define WSPLIT 19456      // 64 * 304
#define WBLK  38912       // 64 cols x 2 splits x 304B
#define SMEM_TOTAL (2 * ABUF + 2 * WBLK)   // 155648
#define NBLOCKS 496       // 62 steps * 8 blocks

__device__ __nv_bfloat16 g_wpack[16 * 19456];  // [net 2][chunk64 8][split 2][n 64][k 152]

// gate col interleave: C = 4*unit + gate (0=i,1=f,2=g,3=o)
__global__ void prep_kernel(const float* __restrict__ eWih, const float* __restrict__ eWhh,
                            const float* __restrict__ ebih, const float* __restrict__ ebhh,
                            const float* __restrict__ dWih, const float* __restrict__ dWhh,
                            const float* __restrict__ dbih, const float* __restrict__ dbhh)
{
    int idx = blockIdx.x * blockDim.x + threadIdx.x;
    if (idx >= 16 * 19456) return;
    int block = idx / 19456;
    int e     = idx % 19456;
    int split = e / 9728;
    int r     = (e % 9728) / 152;
    int k     = e % 152;
    int net = block >> 3, chunk = block & 7;
    int C = chunk * 64 + r;
    int u = C >> 2, g = C & 3;
    int j = g * 128 + u;
    const float* Wih = net ? dWih : eWih;
    const float* Whh = net ? dWhh : eWhh;
    const float* bih = net ? dbih : ebih;
    const float* bhh = net ? dbhh : ebhh;
    float w = 0.f;
    if (k < 128)       w = Whh[j * 128 + k];
    else if (k < 133)  w = Wih[j * 5 + (k - 128)];
    else if (k == 133) w = bih[j] + bhh[j];      // bias lane (A has 1.0 at k=133)
    __nv_bfloat16 hi = __float2bfloat16_rn(w);
    __nv_bfloat16 v  = split ? __float2bfloat16_rn(w - __bfloat162float(hi)) : hi;
    g_wpack[(size_t)block * 19456 + e] = v;
}

__device__ __forceinline__ uint32_t smem_u32(const void* p) {
    uint32_t a;
    asm("{ .reg .u64 t; cvta.to.shared.u64 t, %1; cvt.u32.u64 %0, t; }" : "=r"(a) : "l"(p));
    return a;
}
__device__ __forceinline__ float sigf(float v)   { return __fdividef(1.f, 1.f + __expf(-v)); }
__device__ __forceinline__ float tanhf_(float v) { return fmaf(2.f, sigf(2.f * v), -1.f); }
__device__ __forceinline__ unsigned short bfu(float v) {
    return __bfloat16_as_ushort(__float2bfloat16_rn(v));
}
__device__ __forceinline__ float ubf(unsigned short u) {
    return __bfloat162float(__ushort_as_bfloat16(u));
}

#define LDSX4(r, addr) \
    asm volatile("ldmatrix.sync.aligned.m8n8.x4.shared.b16 {%0,%1,%2,%3}, [%4];" \
        : "=r"((r)[0]), "=r"((r)[1]), "=r"((r)[2]), "=r"((r)[3]) : "r"(addr) : "memory")

#define MMA16816(d, a, b0, b1) \
    asm volatile("mma.sync.aligned.m16n8k16.row.col.f32.bf16.bf16.f32 " \
        "{%0,%1,%2,%3},{%4,%5,%6,%7},{%8,%9},{%0,%1,%2,%3};" \
        : "+f"((d)[0]), "+f"((d)[1]), "+f"((d)[2]), "+f"((d)[3]) \
        : "r"((a)[0]), "r"((a)[1]), "r"((a)[2]), "r"((a)[3]), "r"(b0), "r"(b1))

__device__ __forceinline__ void cp_block(int lin, uint32_t dst, int tid) {
    int gblock = ((lin >= 400) ? 8 : 0) + (lin & 7);
    const char* src = (const char*)g_wpack + (size_t)gblock * WBLK;
    #pragma unroll
    for (int i = 0; i < 5; i++) {   // 2432 x 16B over 512 threads
        int idx = tid + i * BDIM;
        if (idx < WBLK / 16) {
            asm volatile("cp.async.ca.shared.global [%0], [%1], 16;"
                         :: "r"(dst + idx * 16), "l"(src + idx * 16) : "memory");
        }
    }
    asm volatile("cp.async.commit_group;" ::: "memory");
}

__global__ void __launch_bounds__(BDIM, 1)
lstm_mma(const float* __restrict__ x,
         const float* __restrict__ linW,
         const float* __restrict__ linb,
         float* __restrict__ out)
{
    extern __shared__ char smem[];
    const uint32_t sb = smem_u32(smem);
    const int tid  = threadIdx.x;
    const int lane = tid & 31;
    const int w    = tid >> 5;       // 0..15
    const int wm   = w >> 1;         // M-group: rows wm*16..+15
    const int wn   = w & 1;          // N-half: cols wn*32..+31 of 64-col block
    const int base_row = blockIdx.x * 128;

    // zero A region (h=0, x pad lanes=0); B gets fully overwritten by cp.async
    {
        uint4 z = make_uint4(0, 0, 0, 0);
        uint4* p = (uint4*)smem;
        for (int i = tid; i < (2 * ABUF) / 16; i += BDIM) p[i] = z;
    }
    __syncthreads();
    if (tid < 128) {    // bias lane k=133 = 1.0 (hi); persists all 62 steps
        *(unsigned short*)(smem + tid * ROWB + 266) = 0x3F80;
    }

    // cell state: 4 cells per iter x 8 iters (dynamic iter -> local memory)
    float c_loc[32];
    #pragma unroll
    for (int i = 0; i < 32; i++) c_loc[i] = 0.f;

    cp_block(0, sb + SM_B, tid);
    __syncthreads();

    #pragma unroll 1
    for (int t = 0; t < 62; t++) {
        // stage x(t) into k=128..132 (single A buffer; t=49's write persists
        // as decoder static ctx, velocity overwritten by decoder feedback)
        if (t < 50 && tid < 128) {
            const float* xp = x + (size_t)(base_row + tid) * 250 + (size_t)t * 5;
            char* bh = smem + tid * ROWB + 256;   // k=128
            #pragma unroll
            for (int i = 0; i < 5; i++) {
                float v = xp[i];
                unsigned short hu = bfu(v);
                *(unsigned short*)(bh + i * 2) = hu;
                *(unsigned short*)(bh + ABUF + i * 2) = bfu(v - ubf(hu));
            }
        }
        __syncthreads();   // x staged + prior-step epilogue h writes visible

        // load this warp's full-K A fragments ONCE per step (held in regs)
        uint32_t ah[9][4], al[9][4];
        {
            const uint32_t ra0 = sb + (uint32_t)(wm * 16 + (lane & 15)) * ROWB
                               + (uint32_t)(((lane >> 4) << 3) << 1);
            #pragma unroll
            for (int kt = 0; kt < 9; kt++) {
                uint32_t ra = ra0 + (uint32_t)(kt * 32);
                LDSX4(ah[kt], ra);
                LDSX4(al[kt], ra + ABUF);
            }
        }
        __syncthreads();   // all frags loaded before epilogue overwrites h

        #pragma unroll 1
        for (int iter = 0; iter < 8; iter++) {
            const int lin = t * 8 + iter;
            asm volatile("cp.async.wait_group 0;" ::: "memory");
            __syncthreads();
            {
                int nl = lin + 1; if (nl > NBLOCKS - 1) nl = NBLOCKS - 1;
                cp_block(nl, sb + SM_B + (uint32_t)(nl & 1) * WBLK, tid);
            }

            const uint32_t wb = sb + SM_B + (uint32_t)(lin & 1) * WBLK;

            float acc[4][4];
            #pragma unroll
            for (int nt = 0; nt < 4; nt++)
                #pragma unroll
                for (int q = 0; q < 4; q++) acc[nt][q] = 0.f;

            #pragma unroll
            for (int kt = 0; kt < 9; kt++) {
                uint32_t bb[2][4];
                const uint32_t rn = (uint32_t)(wn * 32 + ((lane >> 4) << 3)
                                   + (lane & 7)) * ROWB
                                   + (uint32_t)((kt * 16 + (lane & 8)) << 1);
                LDSX4(bb[0], wb + rn);
                LDSX4(bb[1], wb + rn + 16 * ROWB);
                #pragma unroll
                for (int nt = 0; nt < 4; nt++)
                    MMA16816(acc[nt], ah[kt],
                             bb[nt >> 1][(nt & 1) * 2], bb[nt >> 1][(nt & 1) * 2 + 1]);
                #pragma unroll
                for (int nt = 0; nt < 4; nt++)
                    MMA16816(acc[nt], al[kt],
                             bb[nt >> 1][(nt & 1) * 2], bb[nt >> 1][(nt & 1) * 2 + 1]);
                LDSX4(bb[0], wb + WSPLIT + rn);            // lo overwrites hi regs
                LDSX4(bb[1], wb + WSPLIT + rn + 16 * ROWB);
                #pragma unroll
                for (int nt = 0; nt < 4; nt++)
                    MMA16816(acc[nt], ah[kt],
                             bb[nt >> 1][(nt & 1) * 2], bb[nt >> 1][(nt & 1) * 2 + 1]);
            }

            // epilogue: warp owns rows [wm*16..+15], units [iter*16+wn*8..+7]
            const int cb_u = iter * 16 + wn * 8;
            const bool even = !(lane & 1);
            #pragma unroll
            for (int nt = 0; nt < 4; nt++) {
                float c0 = acc[nt][0], c1 = acc[nt][1];
                float c2 = acc[nt][2], c3 = acc[nt][3];
                float x0 = __shfl_xor_sync(0xffffffffu, c0, 1);
                float x1 = __shfl_xor_sync(0xffffffffu, c1, 1);
                float x2 = __shfl_xor_sync(0xffffffffu, c2, 1);
                float x3 = __shfl_xor_sync(0xffffffffu, c3, 1);
                float iv = even ? c0 : x2;
                float fv = even ? c1 : x3;
                float gv = even ? x0 : c2;
                float ov = even ? x1 : c3;
                int row = wm * 16 + (lane >> 2) + (even ? 0 : 8);
                int ug  = cb_u + nt * 2 + ((lane & 3) >> 1);
                int ci  = iter * 4 + nt;
                float ivs = sigf(iv), fvs = sigf(fv);
                float gvt = tanhf_(gv), ovs = sigf(ov);
                float cn = fmaf(fvs, c_loc[ci], ivs * gvt);
                c_loc[ci] = cn;
                float hv = ovs * tanhf_(cn);
                unsigned short hu = bfu(hv);
                char* bh = smem + row * ROWB + ug * 2;
                *(unsigned short*)bh = hu;
                *(unsigned short*)(bh + ABUF) = bfu(hv - ubf(hu));
            }
        }

        if (t >= 50) {   // pred = h_new @ linW^T + linb; feed back velocity
            __syncthreads();   // all epilogue writes of this step visible
            if (tid < 256) {
                int r = tid & 127, jj = tid >> 7;
                const char* bh = smem + r * ROWB;
                float accp = __ldg(linb + jj);
                const float* lw = linW + jj * 128;
                #pragma unroll 16
                for (int u = 0; u < 128; u++) {
                    float hv = ubf(*(const unsigned short*)(bh + u * 2))
                             + ubf(*(const unsigned short*)(bh + ABUF + u * 2));
                    accp = fmaf(hv, __ldg(lw + u), accp);
                }
                out[((size_t)(base_row + r) * 12 + (t - 50)) * 2 + jj] = accp;
                unsigned short hu = bfu(accp);
                char* bx = smem + r * ROWB + (128 + jj) * 2;
                *(unsigned short*)bx = hu;
                *(unsigned short*)(bx + ABUF) = bfu(accp - ubf(hu));
            }
        }
    }
}

extern "C" void kernel_launch(void* const* d_in, const int* in_sizes, int n_in,
                              void* d_out, int out_size)
{
    const float* x    = (const float*)d_in[0];
    const float* eWih = (const float*)d_in[1];
    const float* eWhh = (const float*)d_in[2];
    const float* ebih = (const float*)d_in[3];
    const float* ebhh = (const float*)d_in[4];
    const float* dWih = (const float*)d_in[5];
    const float* dWhh = (const float*)d_in[6];
    const float* dbih = (const float*)d_in[7];
    const float* dbhh = (const float*)d_in[8];
    const float* lW   = (const float*)d_in[9];
    const float* lb   = (const float*)d_in[10];
    float* out = (float*)d_out;

    cudaFuncSetAttribute(lstm_mma, cudaFuncAttributeMaxDynamicSharedMemorySize, SMEM_TOTAL);

    prep_kernel<<<(16 * 19456 + 255) / 256, 256>>>(eWih, eWhh, ebih, ebhh,
                                                   dWih, dWhh, dbih, dbhh);
    lstm_mma<<<128, BDIM, SMEM_TOTAL>>>(x, lW, lb, out);
}